// round 4
// baseline (speedup 1.0000x reference)
#include <cuda_runtime.h>
#include <cstdint>

#define BB 8

// Scratch
__device__ float2 g_X1[BB * 16 * 256 * 32];   // [b][k][y][c]
__device__ float2 g_G [BB * 256 * 16 * 32];   // [b][y][k][o]
__device__ float2 g_Wt[16 * 32 * 32 * 32];    // [k][h'][c][o]
__device__ float4 g_SD[BB * 16 * 17 * 32];    // [bk][p][o] (Sr,Si,Dr,Di) pre-scaled

// ---------------------------------------------------------------------------
// Compile-time trig table -> FFMA immediates after full unroll.
// ---------------------------------------------------------------------------
struct Trig { float c[256]; float s[256]; };

__host__ __device__ constexpr double tp_cos(double x) {
    double x2 = x * x, t = 1.0, s = 1.0;
    for (int n = 1; n <= 12; n++) { t *= -x2 / double((2 * n - 1) * (2 * n)); s += t; }
    return s;
}
__host__ __device__ constexpr double tp_sin(double x) {
    double x2 = x * x, t = x, s = x;
    for (int n = 1; n <= 12; n++) { t *= -x2 / double((2 * n) * (2 * n + 1)); s += t; }
    return s;
}
__host__ __device__ constexpr Trig make_trig() {
    Trig tr{};
    for (int i = 0; i < 256; i++) {
        int q = i >> 6, r = i & 63;
        double x = 3.14159265358979323846 * double(r) / 128.0;
        double c = tp_cos(x), s = tp_sin(x);
        tr.c[i] = (float)(q == 0 ? c : q == 1 ? -s : q == 2 ? -c :  s);
        tr.s[i] = (float)(q == 0 ? s : q == 1 ?  c : q == 2 ? -s : -c);
    }
    return tr;
}

// ---------------------------------------------------------------------------
// k0: weight reorder, src-linear threads (coalesced reads, scattered stores).
//   src [w][c][o][m1][m2] -> g_Wt[k=m2][h'=w*16+m1][c][o]
// ---------------------------------------------------------------------------
__global__ void k0_reorder_w(const float* __restrict__ wr, const float* __restrict__ wi) {
    int idx = blockIdx.x * 256 + threadIdx.x;     // src-linear, 0..524287
    int m2 = idx & 15;
    int m1 = (idx >> 4) & 15;
    int o  = (idx >> 8) & 31;
    int c  = (idx >> 13) & 31;
    int w  = idx >> 18;
    int dst = ((m2 * 32 + (w * 16 + m1)) * 32 + c) * 32 + o;
    g_Wt[dst] = make_float2(wr[idx], wi[idx]);
}

// ---------------------------------------------------------------------------
// k1: forward W-DFT. 2 warps per row (k-halves), lane = c.
// ---------------------------------------------------------------------------
template<int K0>
__device__ __forceinline__ void fwdW(const float* __restrict__ p, float2* __restrict__ o) {
    constexpr Trig TR = make_trig();
    float re[8], im[8];
    float v0 = p[0], v128 = p[128 * 32];
    float pe = v0 + v128, po = v0 - v128;
#pragma unroll
    for (int j = 0; j < 8; j++) { re[j] = ((K0 + j) & 1) ? po : pe; im[j] = 0.f; }

#pragma unroll
    for (int xp = 1; xp <= 127; xp++) {
        float a = p[xp * 32];
        float b = p[(256 - xp) * 32];
        float s = a + b, d = a - b;
#pragma unroll
        for (int j = 0; j < 8; j++) {
            const int k = K0 + j, id = (k * xp) & 255;
            re[j] = fmaf(s, TR.c[id], re[j]);
            if (k) im[j] = fmaf(d, -TR.s[id], im[j]);
        }
    }
#pragma unroll
    for (int j = 0; j < 8; j++) o[(size_t)(K0 + j) * 8192] = make_float2(re[j], im[j]);
}

__global__ void __launch_bounds__(256) k1_fwd_w(const float* __restrict__ x) {
    int t = threadIdx.x, c = t & 31, w = t >> 5;
    int row = blockIdx.x * 4 + (w >> 1);          // 4 rows per block
    const float* __restrict__ p = x + (size_t)row * 8192 + c;
    int b_ = row >> 8, y = row & 255;
    float2* o = g_X1 + ((size_t)(b_ * 16) * 256 + y) * 32 + c;
    if ((w & 1) == 0) fwdW<0>(p, o);
    else              fwdW<8>(p, o);
}

// ---------------------------------------------------------------------------
// k2a: per (b,k): fwd H-DFT (m-sliced per warp) -> einsum -> pair-combine -> g_SD
// ---------------------------------------------------------------------------
template<int M0, int MC>
__device__ __forceinline__ void phaseA(const float2* __restrict__ xv,
                                       float2* __restrict__ X2, int c) {
    constexpr Trig TR = make_trig();
    float Pr[MC], Pi[MC], Qr[MC], Qi[MC];
    float2 v0 = xv[c], v128 = xv[128 * 32 + c];
#pragma unroll
    for (int j = 0; j < MC; j++) {
        const int m = M0 + 8 * j;
        Pr[j] = (m & 1) ? v0.x - v128.x : v0.x + v128.x;
        Pi[j] = (m & 1) ? v0.y - v128.y : v0.y + v128.y;
        Qr[j] = 0.f; Qi[j] = 0.f;
    }
#pragma unroll
    for (int yp = 1; yp <= 127; yp++) {
        float2 a = xv[yp * 32 + c];
        float2 b = xv[(256 - yp) * 32 + c];
        float sx = a.x + b.x, sy = a.y + b.y;
        float dx = a.x - b.x, dy = a.y - b.y;
#pragma unroll
        for (int j = 0; j < MC; j++) {
            const int m = M0 + 8 * j, id = (m * yp) & 255;
            Pr[j] = fmaf(sx, TR.c[id], Pr[j]);
            Pi[j] = fmaf(sy, TR.c[id], Pi[j]);
            if (m) {
                Qr[j] = fmaf(dx, TR.s[id], Qr[j]);
                Qi[j] = fmaf(dy, TR.s[id], Qi[j]);
            }
        }
    }
#pragma unroll
    for (int j = 0; j < MC; j++) {
        const int m = M0 + 8 * j;
        if (m == 0) {
            X2[c] = make_float2(Pr[j], Pi[j]);
        } else if (m == 16) {
            X2[16 * 32 + c] = make_float2(Pr[j] - Qi[j], Pi[j] + Qr[j]);
        } else {
            X2[m * 32 + c]        = make_float2(Pr[j] + Qi[j], Pi[j] - Qr[j]);
            X2[(32 - m) * 32 + c] = make_float2(Pr[j] - Qi[j], Pi[j] + Qr[j]);
        }
    }
}

__global__ void __launch_bounds__(256) k2a_mid() {
    __shared__ float2 X2[32 * 32];
    __shared__ float2 OB[32 * 32];
    int t = threadIdx.x, w = t >> 5, c = t & 31;
    int bk = blockIdx.x;
    int k = bk & 15;

    const float2* __restrict__ xv = g_X1 + (size_t)bk * 8192;   // [y][c]
    switch (w) {
        case 0: phaseA<0, 3>(xv, X2, c); break;   // m = 0, 8, 16
        case 1: phaseA<1, 2>(xv, X2, c); break;
        case 2: phaseA<2, 2>(xv, X2, c); break;
        case 3: phaseA<3, 2>(xv, X2, c); break;
        case 4: phaseA<4, 2>(xv, X2, c); break;
        case 5: phaseA<5, 2>(xv, X2, c); break;
        case 6: phaseA<6, 2>(xv, X2, c); break;
        default: phaseA<7, 2>(xv, X2, c); break;
    }
    __syncthreads();

    // einsum over c: OB[h][o] = sum_c X2[h][c] * Wt[k][h][c][o]
    const float2* __restrict__ wtk = g_Wt + (size_t)k * 32768;
#pragma unroll
    for (int j = 0; j < 4; j++) {
        int h = w * 4 + j;
        float ar = 0.f, ai = 0.f;
        const float2* __restrict__ xr = X2 + h * 32;
        const float2* __restrict__ wrow = wtk + (size_t)h * 1024 + c;
#pragma unroll
        for (int cc = 0; cc < 32; cc++) {
            float2 xx = xr[cc];
            float2 ww = wrow[cc * 32];
            ar = fmaf(xx.x, ww.x, ar); ar = fmaf(-xx.y, ww.y, ar);
            ai = fmaf(xx.x, ww.y, ai); ai = fmaf( xx.y, ww.x, ai);
        }
        OB[h * 32 + c] = make_float2(ar, ai);
    }
    __syncthreads();

    // pair-combine + scale -> g_SD[bk][p][o]
    float sc = (k == 0) ? (1.0f / 65536.0f) : (2.0f / 65536.0f);
    for (int tt = t; tt < 17 * 32; tt += 256) {
        int p = tt >> 5, o = tt & 31;
        float2 A = OB[p * 32 + o];
        float4 r;
        if (p == 0 || p == 16) {
            r = make_float4(A.x * sc, A.y * sc, -A.x * sc, -A.y * sc);
        } else {
            float2 Bv = OB[(32 - p) * 32 + o];
            r = make_float4((A.x + Bv.x) * sc, (A.y + Bv.y) * sc,
                            (A.x - Bv.x) * sc, (A.y - Bv.y) * sc);
        }
        g_SD[(size_t)bk * 544 + tt] = r;
    }
}

// ---------------------------------------------------------------------------
// k2b: inverse H, templated yp ranges; grid = 128 bk * 2 halves, 4 warps/block.
// ---------------------------------------------------------------------------
template<int Y0, int Y1>
__device__ __forceinline__ void invH(const float4* __restrict__ sd,
                                     float2* __restrict__ g) {
    constexpr Trig TR = make_trig();
#pragma unroll
    for (int yp = Y0; yp < Y1; yp++) {
        float U1 = 0.f, U2 = 0.f, V1 = 0.f, V2 = 0.f;
#pragma unroll
        for (int p = 0; p < 17; p++) {
            const int id = (p * yp) & 255;
            U1 = fmaf(sd[p].x, TR.c[id], U1);
            U2 = fmaf(sd[p].y, TR.c[id], U2);
            if (p) {
                V1 = fmaf(sd[p].w, TR.s[id], V1);
                V2 = fmaf(sd[p].z, TR.s[id], V2);
            }
        }
        g[(size_t)yp * 512] = make_float2(U1 - V1, U2 + V2);
        if (yp != 0 && yp != 128)
            g[(size_t)(256 - yp) * 512] = make_float2(U1 + V1, U2 - V2);
    }
}

__global__ void __launch_bounds__(128) k2b_invh() {
    int t = threadIdx.x, w = t >> 5, c = t & 31;
    int bk = blockIdx.x >> 1;
    int r = (blockIdx.x & 1) * 4 + w;   // 0..7 range selector

    float4 sd[17];
#pragma unroll
    for (int p = 0; p < 17; p++) sd[p] = g_SD[(size_t)bk * 544 + p * 32 + c];

    float2* __restrict__ g = g_G + ((size_t)(bk >> 4) * 4096 + (bk & 15)) * 32 + c;
    switch (r) {
        case 0: invH<0,   16>(sd, g); break;
        case 1: invH<16,  32>(sd, g); break;
        case 2: invH<32,  48>(sd, g); break;
        case 3: invH<48,  64>(sd, g); break;
        case 4: invH<64,  80>(sd, g); break;
        case 5: invH<80,  96>(sd, g); break;
        case 6: invH<96, 112>(sd, g); break;
        default: invH<112, 129>(sd, g); break;
    }
}

// ---------------------------------------------------------------------------
// k3: inverse W. 2 warps per row (xp-halves), lane = o.
// ---------------------------------------------------------------------------
template<int X0, int X1>
__device__ __forceinline__ void invW(const float* __restrict__ Gr,
                                     const float* __restrict__ Gi,
                                     float* __restrict__ ob) {
    constexpr Trig TR = make_trig();
#pragma unroll
    for (int xp = X0; xp < X1; xp++) {
        float A = 0.f, B = 0.f;
#pragma unroll
        for (int k = 0; k < 16; k++) {
            const int id = (k * xp) & 255;
            A = fmaf(Gr[k], TR.c[id], A);
            if (k) B = fmaf(Gi[k], TR.s[id], B);
        }
        ob[xp * 32] = A - B;
        if (xp != 0 && xp != 128)
            ob[(256 - xp) * 32] = A + B;
    }
}

__global__ void __launch_bounds__(256) k3_inv_w(float* __restrict__ out) {
    int t = threadIdx.x, o = t & 31, w = t >> 5;
    int row = blockIdx.x * 4 + (w >> 1);
    const float2* __restrict__ g = g_G + (size_t)row * 512 + o;

    float Gr[16], Gi[16];
#pragma unroll
    for (int k = 0; k < 16; k++) { float2 v = g[k * 32]; Gr[k] = v.x; Gi[k] = v.y; }

    float* __restrict__ ob = out + (size_t)row * 8192 + o;
    if ((w & 1) == 0) invW<0, 65>(Gr, Gi, ob);
    else              invW<65, 129>(Gr, Gi, ob);
}

// ---------------------------------------------------------------------------
extern "C" void kernel_launch(void* const* d_in, const int* in_sizes, int n_in,
                              void* d_out, int out_size) {
    const float* x  = (const float*)d_in[0];
    const float* wr = (const float*)d_in[1];
    const float* wi = (const float*)d_in[2];
    float* out = (float*)d_out;

    k0_reorder_w<<<2048, 256>>>(wr, wi);
    k1_fwd_w   <<<512, 256>>>(x);
    k2a_mid    <<<128, 256>>>();
    k2b_invh   <<<256, 128>>>();
    k3_inv_w   <<<512, 256>>>(out);
}